// round 2
// baseline (speedup 1.0000x reference)
#include <cuda_runtime.h>

// Problem: B=128, N=128, K=12, D=256
//   feat[b,n,k,:] = concat(extra[b,n,:] * nbr[b,n,k,:], wgt[b,n,k])   [K, D+1]
//   a1 = leaky_relu(feat @ w1, 0.2)                                    [K, D]
//   logit[k] = a1[k,:] . w2[:,0]                                       [K]
//   alpha = softmax_k(logit)
//   agg = sum_k alpha[k] * nbr[k,:]                                    [D]
//   out = relu(concat(self, agg) @ w3)                                 [D]
// One CTA per (b,n), 256 threads, thread = output column.

#define DD   256
#define KN   12
#define TPB  256

__global__ __launch_bounds__(TPB, 4)
void gagg_kernel(const float* __restrict__ self_v,
                 const float* __restrict__ nbr,
                 const float* __restrict__ wgt,
                 const float* __restrict__ extra,
                 const float* __restrict__ w1,
                 const float* __restrict__ w2,
                 const float* __restrict__ w3,
                 float* __restrict__ out)
{
    __shared__ float s_prod[KN][DD];   // extra * neighbor  (feat columns 0..255)
    __shared__ float s_nb[KN][DD];     // raw neighbor (for aggregation)
    __shared__ float s_cat[2 * DD];    // [self | agg]
    __shared__ float s_wt[KN];         // neighbor_weight (feat column 256)
    __shared__ float s_red[KN][8];     // per-warp reduction partials

    const int bn   = blockIdx.x;       // fused (b, n) index, 0..16383
    const int tid  = threadIdx.x;      // output column d'
    const long base  = (long)bn * DD;
    const long nbase = (long)bn * (KN * DD);

    // ---- stage inputs ----
    const float ext = extra[base + tid];
    s_cat[tid] = self_v[base + tid];
    if (tid < KN) s_wt[tid] = wgt[(long)bn * KN + tid];
#pragma unroll
    for (int k = 0; k < KN; k++) {
        float v = nbr[nbase + k * DD + tid];
        s_nb[k][tid]   = v;
        s_prod[k][tid] = ext * v;
    }
    __syncthreads();

    // ---- z[k, tid] = feat[k,:] . w1[:, tid]  (register-resident acc over 12 k) ----
    float acc[KN];
    {
        const float wlast = __ldg(&w1[(long)DD * DD + tid]); // w1 row f = 256
#pragma unroll
        for (int k = 0; k < KN; k++) acc[k] = s_wt[k] * wlast;
    }

#pragma unroll 2
    for (int f = 0; f < DD; f += 4) {
        const float a0 = __ldg(&w1[(f + 0) * DD + tid]);
        const float a1 = __ldg(&w1[(f + 1) * DD + tid]);
        const float a2 = __ldg(&w1[(f + 2) * DD + tid]);
        const float a3 = __ldg(&w1[(f + 3) * DD + tid]);
#pragma unroll
        for (int k = 0; k < KN; k++) {
            const float4 p = *reinterpret_cast<const float4*>(&s_prod[k][f]);
            float a = acc[k];
            a = fmaf(p.x, a0, a);
            a = fmaf(p.y, a1, a);
            a = fmaf(p.z, a2, a);
            a = fmaf(p.w, a3, a);
            acc[k] = a;
        }
    }

    // ---- logit[k] = sum_tid leaky_relu(z) * w2[tid]   (block reduce) ----
    {
        const float w2t  = __ldg(&w2[tid]);
        const int   lane = tid & 31;
        const int   wid  = tid >> 5;
#pragma unroll
        for (int k = 0; k < KN; k++) {
            float v = acc[k];
            v = (v > 0.0f) ? v : 0.2f * v;   // leaky_relu, slope 0.2
            v *= w2t;
#pragma unroll
            for (int o = 16; o > 0; o >>= 1)
                v += __shfl_xor_sync(0xffffffffu, v, o);
            if (lane == 0) s_red[k][wid] = v;
        }
    }
    __syncthreads();

    // ---- softmax over K (computed redundantly per thread; broadcast LDS) ----
    float alpha[KN];
    {
        float logit[KN];
#pragma unroll
        for (int k = 0; k < KN; k++) {
            float s = 0.0f;
#pragma unroll
            for (int w = 0; w < 8; w++) s += s_red[k][w];
            logit[k] = s;
        }
        float m = logit[0];
#pragma unroll
        for (int k = 1; k < KN; k++) m = fmaxf(m, logit[k]);
        float se = 0.0f;
#pragma unroll
        for (int k = 0; k < KN; k++) { alpha[k] = expf(logit[k] - m); se += alpha[k]; }
        const float inv = 1.0f / se;
#pragma unroll
        for (int k = 0; k < KN; k++) alpha[k] *= inv;
    }

    // ---- agg[tid] = sum_k alpha[k] * nbr[k, tid] ----
    {
        float aggv = 0.0f;
#pragma unroll
        for (int k = 0; k < KN; k++) aggv = fmaf(alpha[k], s_nb[k][tid], aggv);
        s_cat[DD + tid] = aggv;
    }
    __syncthreads();

    // ---- out[tid] = relu( cat[0:512] . w3[:, tid] ) ----
    {
        float o = 0.0f;
#pragma unroll 4
        for (int j = 0; j < 2 * DD; j += 4) {
            const float4 c = *reinterpret_cast<const float4*>(&s_cat[j]);
            o = fmaf(c.x, __ldg(&w3[(j + 0) * DD + tid]), o);
            o = fmaf(c.y, __ldg(&w3[(j + 1) * DD + tid]), o);
            o = fmaf(c.z, __ldg(&w3[(j + 2) * DD + tid]), o);
            o = fmaf(c.w, __ldg(&w3[(j + 3) * DD + tid]), o);
        }
        out[base + tid] = fmaxf(o, 0.0f);
    }
}

extern "C" void kernel_launch(void* const* d_in, const int* in_sizes, int n_in,
                              void* d_out, int out_size)
{
    // metadata order: self_vectors, neighbor_vector, masks, neighbor_weight,
    //                 extra_vector, w1, w2, w3, batch_size
    const float* self_v = (const float*)d_in[0];
    const float* nbr    = (const float*)d_in[1];
    // d_in[2] = masks (unused by reference)
    const float* wgt    = (const float*)d_in[3];
    const float* extra  = (const float*)d_in[4];
    const float* w1     = (const float*)d_in[5];
    const float* w2     = (const float*)d_in[6];
    const float* w3     = (const float*)d_in[7];
    float* out = (float*)d_out;

    const int BN = 128 * 128; // B * N
    gagg_kernel<<<BN, TPB>>>(self_v, nbr, wgt, extra, w1, w2, w3, out);
}

// round 5
// speedup vs baseline: 3.4169x; 3.4169x over previous
#include <cuda_runtime.h>
#include <cuda_bf16.h>
#include <cstdint>

// ============================================================================
// GlobalAggregator — warp-level HMMA (mma.sync bf16, 2-way split) for sm_103
// B=128, N=128, K=12, D=256
// Phase 1: per-warp bn pair: Z[16,256] = feat[16,256] @ w1[0:256]  (mma)
//          + wgt ⊗ w1[256] (exact fp32 epilogue) -> lrelu -> ·w2 -> softmax
//          -> agg = Σ alpha·nbr (fp32)
// Phase 2: out = relu(concat(self, agg)[16384,512] @ w3)  (mma)
// ============================================================================

#define KS1 16
#define KS2 32
#define ROWB 24              // ushorts per n-row: 16 used + 8 pad = 48B
                             // (16B-aligned rows for ldmatrix; 12-bank stride
                             //  -> 8 rows hit 8 distinct banks, conflict-free)
#define CB  (256 * ROWB * 2) // bytes per chunk half: 12288

// ---- device scratch ----
__device__ __align__(128) unsigned short g_w1t_hi[KS1 * 256 * ROWB];
__device__ __align__(128) unsigned short g_w1t_lo[KS1 * 256 * ROWB];
__device__ __align__(128) unsigned short g_w3t_hi[KS2 * 256 * ROWB];
__device__ __align__(128) unsigned short g_w3t_lo[KS2 * 256 * ROWB];
__device__ __align__(16) float g_agg[16384 * 256];

// ---- smem offsets (bytes) ----
#define OFF_B(s) (1024 + (s) * (2 * CB))     // hi @ +0, lo @ +CB
#define OFF_EXT   50176      // 8*256 floats
#define OFF_W2    58368      // 256 floats
#define OFF_W1L   59392      // 256 floats
#define OFF_WGT   60416      // 8*12 floats
#define OFF_LOGIT 60800      // 8*16 floats
#define OFF_ALPHA 61312      // 8*12 floats
#define SMEM1     61696
#define SMEM2     50176

// ============================================================================
// PTX helpers (baseline sm_80/sm_90 features only — nothing 'a'-gated)
// ============================================================================
__device__ __forceinline__ uint32_t smem_u32(const void* p) {
    uint32_t r;
    asm("{ .reg .u64 t; cvta.to.shared.u64 t, %1; cvt.u32.u64 %0, t; }"
        : "=r"(r) : "l"(p));
    return r;
}
__device__ __forceinline__ void mbar_init(uint32_t a, uint32_t cnt) {
    asm volatile("mbarrier.init.shared.b64 [%0], %1;" :: "r"(a), "r"(cnt) : "memory");
}
__device__ __forceinline__ void mbar_expect_tx(uint32_t a, uint32_t b) {
    asm volatile("mbarrier.arrive.expect_tx.shared.b64 _, [%0], %1;"
                 :: "r"(a), "r"(b) : "memory");
}
__device__ __forceinline__ void mbar_wait(uint32_t a, uint32_t ph) {
    asm volatile(
        "{\n\t.reg .pred P;\n\t"
        "WL_%=:\n\t"
        "mbarrier.try_wait.parity.acquire.cta.shared::cta.b64 P, [%0], %1, 0x989680;\n\t"
        "@P bra.uni WD_%=;\n\t"
        "bra.uni WL_%=;\n\t"
        "WD_%=:\n\t}"
        :: "r"(a), "r"(ph) : "memory");
}
__device__ __forceinline__ void bulk_g2s(uint32_t dst, const void* src,
                                         uint32_t bytes, uint32_t mbar) {
    asm volatile(
        "cp.async.bulk.shared::cluster.global.mbarrier::complete_tx::bytes [%0], [%1], %2, [%3];"
        :: "r"(dst), "l"(src), "r"(bytes), "r"(mbar) : "memory");
}
__device__ __forceinline__ void ldsm4(uint32_t* r, uint32_t addr) {
    asm volatile("ldmatrix.sync.aligned.m8n8.x4.shared.b16 {%0,%1,%2,%3}, [%4];"
                 : "=r"(r[0]), "=r"(r[1]), "=r"(r[2]), "=r"(r[3]) : "r"(addr));
}
__device__ __forceinline__ void mma16816(float* c, const uint32_t* a,
                                         uint32_t b0, uint32_t b1) {
    asm volatile(
        "mma.sync.aligned.m16n8k16.row.col.f32.bf16.bf16.f32 "
        "{%0,%1,%2,%3}, {%4,%5,%6,%7}, {%8,%9}, {%0,%1,%2,%3};"
        : "+f"(c[0]), "+f"(c[1]), "+f"(c[2]), "+f"(c[3])
        : "r"(a[0]), "r"(a[1]), "r"(a[2]), "r"(a[3]), "r"(b0), "r"(b1));
}
__device__ __forceinline__ void split2(float v0, float v1, uint32_t& h, uint32_t& l) {
    __nv_bfloat162 hh = __floats2bfloat162_rn(v0, v1);
    float r0 = v0 - __bfloat162float(hh.x);
    float r1 = v1 - __bfloat162float(hh.y);
    __nv_bfloat162 ll = __floats2bfloat162_rn(r0, r1);
    h = *reinterpret_cast<uint32_t*>(&hh);
    l = *reinterpret_cast<uint32_t*>(&ll);
}

// ============================================================================
// prep: transpose + split weights into [chunk][n][k16] (48B rows)
// ============================================================================
__global__ void prep_w1(const float* __restrict__ w1) {
    int i = blockIdx.x * blockDim.x + threadIdx.x;       // c*4096 + n*16 + kk
    if (i >= KS1 * 256 * 16) return;
    int kk = i & 15, n = (i >> 4) & 255, c = i >> 12;
    float v = w1[(c * 16 + kk) * 256 + n];
    __nv_bfloat16 h = __float2bfloat16(v);
    __nv_bfloat16 l = __float2bfloat16(v - __bfloat162float(h));
    int dst = (c * 256 + n) * ROWB + kk;
    g_w1t_hi[dst] = __bfloat16_as_ushort(h);
    g_w1t_lo[dst] = __bfloat16_as_ushort(l);
}
__global__ void prep_w3(const float* __restrict__ w3) {
    int i = blockIdx.x * blockDim.x + threadIdx.x;
    if (i >= KS2 * 256 * 16) return;
    int kk = i & 15, n = (i >> 4) & 255, c = i >> 12;
    float v = w3[(c * 16 + kk) * 256 + n];
    __nv_bfloat16 h = __float2bfloat16(v);
    __nv_bfloat16 l = __float2bfloat16(v - __bfloat162float(h));
    int dst = (c * 256 + n) * ROWB + kk;
    g_w3t_hi[dst] = __bfloat16_as_ushort(h);
    g_w3t_lo[dst] = __bfloat16_as_ushort(l);
}

// ============================================================================
// Phase 1 — grid 2048, 256 thr; warp = one bn pair
// ============================================================================
__global__ __launch_bounds__(256)
void p1_kernel(const float* __restrict__ nbr, const float* __restrict__ wgt,
               const float* __restrict__ extra, const float* __restrict__ w1,
               const float* __restrict__ w2) {
    extern __shared__ char smem[];
    const uint32_t sb = smem_u32(smem);
    const int tid = threadIdx.x, wid = tid >> 5, lane = tid & 31;
    const int bn0 = blockIdx.x * 8;

    float* s_ext = (float*)(smem + OFF_EXT);
    float* s_w2  = (float*)(smem + OFF_W2);
    float* s_w1l = (float*)(smem + OFF_W1L);
    float* s_wgt = (float*)(smem + OFF_WGT);
    float* s_log = (float*)(smem + OFF_LOGIT);
    float* s_alp = (float*)(smem + OFF_ALPHA);

    if (tid == 0) { mbar_init(sb + 0, 1); mbar_init(sb + 8, 1); }
    for (int i = tid; i < 2048; i += 256)
        s_ext[i] = extra[(long)bn0 * 256 + i];
    s_w2[tid]  = w2[tid];
    s_w1l[tid] = w1[256 * 256 + tid];
    if (tid < 96) s_wgt[tid] = wgt[(long)bn0 * 12 + tid];
    __syncthreads();

    if (tid == 0) {
        mbar_expect_tx(sb + 0, 2 * CB);
        bulk_g2s(sb + OFF_B(0),      g_w1t_hi, CB, sb + 0);
        bulk_g2s(sb + OFF_B(0) + CB, g_w1t_lo, CB, sb + 0);
        mbar_expect_tx(sb + 8, 2 * CB);
        bulk_g2s(sb + OFF_B(1),      g_w1t_hi + CB / 2, CB, sb + 8);
        bulk_g2s(sb + OFF_B(1) + CB, g_w1t_lo + CB / 2, CB, sb + 8);
    }

    const int  p   = wid;
    const long bn  = bn0 + p;
    const int  l4  = lane & 3, grp = lane >> 2;
    const int  r1  = grp + 8;
    const bool hr1 = (r1 < 12);
    // ldmatrix per-lane row offset (within a 16-n pair-tile):
    //  lanes 0-7:   n row (lane&7),   k-half 0
    //  lanes 8-15:  n row (lane&7),   k-half 1
    //  lanes 16-23: n row 8+(lane&7), k-half 0
    //  lanes 24-31: n row 8+(lane&7), k-half 1
    const uint32_t rowoff =
        ((((lane >> 3) & 2) * 4 + (lane & 7)) * ROWB + ((lane >> 3) & 1) * 8) * 2;

    float acc[128];
#pragma unroll
    for (int i = 0; i < 128; i++) acc[i] = 0.0f;

    float2 e0, e1, nA0, nA1, nB0, nB1;
    {
        const int k0 = l4 * 2;
        e0 = *(const float2*)&s_ext[p * 256 + k0];
        e1 = *(const float2*)&s_ext[p * 256 + k0 + 8];
        const float* nb = nbr + ((bn * 12 + grp) << 8) + k0;
        nA0 = *(const float2*)nb; nA1 = *(const float2*)(nb + 8);
        nB0 = make_float2(0, 0);  nB1 = make_float2(0, 0);
        if (hr1) {
            const float* nc = nbr + ((bn * 12 + r1) << 8) + k0;
            nB0 = *(const float2*)nc; nB1 = *(const float2*)(nc + 8);
        }
    }

#pragma unroll 1
    for (int c = 0; c < KS1; c++) {
        const int s = c & 1, ph = (c >> 1) & 1;

        uint32_t ah[4], al[4];
        split2(e0.x * nA0.x, e0.y * nA0.y, ah[0], al[0]);
        split2(e0.x * nB0.x, e0.y * nB0.y, ah[1], al[1]);
        split2(e1.x * nA1.x, e1.y * nA1.y, ah[2], al[2]);
        split2(e1.x * nB1.x, e1.y * nB1.y, ah[3], al[3]);

        if (c + 1 < KS1) {                       // prefetch next k-step
            const int k0 = (c + 1) * 16 + l4 * 2;
            e0 = *(const float2*)&s_ext[p * 256 + k0];
            e1 = *(const float2*)&s_ext[p * 256 + k0 + 8];
            const float* nb = nbr + ((bn * 12 + grp) << 8) + k0;
            nA0 = *(const float2*)nb; nA1 = *(const float2*)(nb + 8);
            if (hr1) {
                const float* nc = nbr + ((bn * 12 + r1) << 8) + k0;
                nB0 = *(const float2*)nc; nB1 = *(const float2*)(nc + 8);
            }
        }

        mbar_wait(sb + s * 8, ph);
        const uint32_t sBh = sb + OFF_B(s), sBl = sBh + CB;
#pragma unroll
        for (int np = 0; np < 16; np++) {
            uint32_t bh[4], bl[4];
            ldsm4(bh, sBh + np * (16 * ROWB * 2) + rowoff);
            ldsm4(bl, sBl + np * (16 * ROWB * 2) + rowoff);
            float* c0 = acc + np * 8;
            float* c1 = acc + np * 8 + 4;
            mma16816(c0, ah, bh[0], bh[1]);
            mma16816(c1, ah, bh[2], bh[3]);
            mma16816(c0, al, bh[0], bh[1]);
            mma16816(c1, al, bh[2], bh[3]);
            mma16816(c0, ah, bl[0], bl[1]);
            mma16816(c1, ah, bl[2], bl[3]);
        }
        __syncthreads();
        if (tid == 0 && c + 2 < KS1) {
            mbar_expect_tx(sb + s * 8, 2 * CB);
            bulk_g2s(sb + OFF_B(s),      g_w1t_hi + (c + 2) * (CB / 2), CB, sb + s * 8);
            bulk_g2s(sb + OFF_B(s) + CB, g_w1t_lo + (c + 2) * (CB / 2), CB, sb + s * 8);
        }
    }

    // ---- epilogue: + wgt⊗w1[256], lrelu, ·w2, row-reduce ----
    const float wr0 = s_wgt[p * 12 + grp];
    const float wr1 = hr1 ? s_wgt[p * 12 + r1] : 0.0f;
    float p0 = 0.0f, p1 = 0.0f;
#pragma unroll
    for (int nt = 0; nt < 32; nt++) {
        const int col = nt * 8 + l4 * 2;
        const float u0 = s_w1l[col], u1 = s_w1l[col + 1];
        const float v0 = s_w2[col],  v1 = s_w2[col + 1];
        float z;
        z = acc[nt * 4 + 0] + wr0 * u0; z = (z > 0.f) ? z : 0.2f * z; p0 = fmaf(z, v0, p0);
        z = acc[nt * 4 + 1] + wr0 * u1; z = (z > 0.f) ? z : 0.2f * z; p0 = fmaf(z, v1, p0);
        z = acc[nt * 4 + 2] + wr1 * u0; z = (z > 0.f) ? z : 0.2f * z; p1 = fmaf(z, v0, p1);
        z = acc[nt * 4 + 3] + wr1 * u1; z = (z > 0.f) ? z : 0.2f * z; p1 = fmaf(z, v1, p1);
    }
    p0 += __shfl_xor_sync(0xffffffffu, p0, 1);
    p0 += __shfl_xor_sync(0xffffffffu, p0, 2);
    p1 += __shfl_xor_sync(0xffffffffu, p1, 1);
    p1 += __shfl_xor_sync(0xffffffffu, p1, 2);
    if (l4 == 0) {
        s_log[p * 16 + grp] = p0;
        if (hr1) s_log[p * 16 + r1] = p1;
    }
    __syncwarp();

    if (lane < 12) {
        const float* lg = &s_log[p * 16];
        float m = lg[0];
#pragma unroll
        for (int i = 1; i < 12; i++) m = fmaxf(m, lg[i]);
        float se = 0.0f;
#pragma unroll
        for (int i = 0; i < 12; i++) se += expf(lg[i] - m);
        s_alp[p * 12 + lane] = expf(lg[lane] - m) / se;
    }
    __syncwarp();

    {   // agg: each lane 8 contiguous d
        const int d0 = lane * 8;
        float4 s0 = make_float4(0, 0, 0, 0), s1 = make_float4(0, 0, 0, 0);
#pragma unroll
        for (int k = 0; k < 12; k++) {
            const float a = s_alp[p * 12 + k];
            const float4* src = (const float4*)&nbr[((bn * 12 + k) << 8) + d0];
            float4 x = src[0], y = src[1];
            s0.x = fmaf(a, x.x, s0.x); s0.y = fmaf(a, x.y, s0.y);
            s0.z = fmaf(a, x.z, s0.z); s0.w = fmaf(a, x.w, s0.w);
            s1.x = fmaf(a, y.x, s1.x); s1.y = fmaf(a, y.y, s1.y);
            s1.z = fmaf(a, y.z, s1.z); s1.w = fmaf(a, y.w, s1.w);
        }
        float4* dst = (float4*)&g_agg[(bn << 8) + d0];
        dst[0] = s0; dst[1] = s1;
    }
}

// ============================================================================
// Phase 2 — grid 128, 256 thr; warp = 16 bn rows; out = relu(cat @ w3)
// ============================================================================
__global__ __launch_bounds__(256)
void p2_kernel(const float* __restrict__ self_v, float* __restrict__ out) {
    extern __shared__ char smem[];
    const uint32_t sb = smem_u32(smem);
    const int tid = threadIdx.x, wid = tid >> 5, lane = tid & 31;
    const int mb = blockIdx.x * 128 + wid * 16;

    if (tid == 0) { mbar_init(sb + 0, 1); mbar_init(sb + 8, 1); }
    __syncthreads();
    if (tid == 0) {
        mbar_expect_tx(sb + 0, 2 * CB);
        bulk_g2s(sb + OFF_B(0),      g_w3t_hi, CB, sb + 0);
        bulk_g2s(sb + OFF_B(0) + CB, g_w3t_lo, CB, sb + 0);
        mbar_expect_tx(sb + 8, 2 * CB);
        bulk_g2s(sb + OFF_B(1),      g_w3t_hi + CB / 2, CB, sb + 8);
        bulk_g2s(sb + OFF_B(1) + CB, g_w3t_lo + CB / 2, CB, sb + 8);
    }

    const int l4 = lane & 3, grp = lane >> 2;
    const long m0 = mb + grp, m1 = mb + grp + 8;
    const uint32_t rowoff =
        ((((lane >> 3) & 2) * 4 + (lane & 7)) * ROWB + ((lane >> 3) & 1) * 8) * 2;

    float acc[128];
#pragma unroll
    for (int i = 0; i < 128; i++) acc[i] = 0.0f;

    float2 nA0, nA1, nB0, nB1;
    {
        const int k0 = l4 * 2;
        nA0 = *(const float2*)&self_v[(m0 << 8) + k0];
        nA1 = *(const float2*)&self_v[(m0 << 8) + k0 + 8];
        nB0 = *(const float2*)&self_v[(m1 << 8) + k0];
        nB1 = *(const float2*)&self_v[(m1 << 8) + k0 + 8];
    }

#pragma unroll 1
    for (int c = 0; c < KS2; c++) {
        const int s = c & 1, ph = (c >> 1) & 1;

        uint32_t ah[4], al[4];
        split2(nA0.x, nA0.y, ah[0], al[0]);
        split2(nB0.x, nB0.y, ah[1], al[1]);
        split2(nA1.x, nA1.y, ah[2], al[2]);
        split2(nB1.x, nB1.y, ah[3], al[3]);

        if (c + 1 < KS2) {
            const int cn = c + 1;
            const int k0 = (cn & 15) * 16 + l4 * 2;
            const float* base = (cn < 16) ? self_v : g_agg;
            nA0 = *(const float2*)&base[(m0 << 8) + k0];
            nA1 = *(const float2*)&base[(m0 << 8) + k0 + 8];
            nB0 = *(const float2*)&base[(m1 << 8) + k0];
            nB1 = *(const float2*)&base[(m1 << 8) + k0 + 8];
        }

        mbar_wait(sb + s * 8, ph);
        const uint32_t sBh = sb + OFF_B(s), sBl = sBh + CB;
#pragma unroll
        for (int np = 0; np < 16; np++) {
            uint32_t bh[4], bl[4];
            ldsm4(bh, sBh + np * (16 * ROWB * 2) + rowoff);
            ldsm4(bl, sBl + np * (16 * ROWB * 2) + rowoff);
            float* c0 = acc + np * 8;
            float* c1 = acc + np * 8 + 4;
            mma16816(c0, ah, bh[0], bh[1]);
            mma16816(c1, ah, bh[2], bh[3]);
            mma16816(c0, al, bh[0], bh[1]);
            mma16816(c1, al, bh[2], bh[3]);
            mma16816(c0, ah, bl[0], bl[1]);
            mma16816(c1, ah, bl[2], bl[3]);
        }
        __syncthreads();
        if (tid == 0 && c + 2 < KS2) {
            mbar_expect_tx(sb + s * 8, 2 * CB);
            bulk_g2s(sb + OFF_B(s),      g_w3t_hi + (c + 2) * (CB / 2), CB, sb + s * 8);
            bulk_g2s(sb + OFF_B(s) + CB, g_w3t_lo + (c + 2) * (CB / 2), CB, sb + s * 8);
        }
    }

#pragma unroll
    for (int nt = 0; nt < 32; nt++) {
        const int col = nt * 8 + l4 * 2;
        float2 o0 = make_float2(fmaxf(acc[nt * 4 + 0], 0.f), fmaxf(acc[nt * 4 + 1], 0.f));
        float2 o1 = make_float2(fmaxf(acc[nt * 4 + 2], 0.f), fmaxf(acc[nt * 4 + 3], 0.f));
        *(float2*)&out[(m0 << 8) + col] = o0;
        *(float2*)&out[(m1 << 8) + col] = o1;
    }
}

// ============================================================================
extern "C" void kernel_launch(void* const* d_in, const int* in_sizes, int n_in,
                              void* d_out, int out_size) {
    const float* self_v = (const float*)d_in[0];
    const float* nbr    = (const float*)d_in[1];
    // d_in[2] = masks (unused by reference)
    const float* wgt    = (const float*)d_in[3];
    const float* extra  = (const float*)d_in[4];
    const float* w1     = (const float*)d_in[5];
    const float* w2     = (const float*)d_in[6];
    const float* w3     = (const float*)d_in[7];
    float* out = (float*)d_out;

    cudaFuncSetAttribute(p1_kernel, cudaFuncAttributeMaxDynamicSharedMemorySize, SMEM1);
    cudaFuncSetAttribute(p2_kernel, cudaFuncAttributeMaxDynamicSharedMemorySize, SMEM2);

    prep_w1<<<256, 256>>>(w1);
    prep_w3<<<512, 256>>>(w3);
    p1_kernel<<<2048, 256, SMEM1>>>(nbr, wgt, extra, w1, w2);
    p2_kernel<<<128, 256, SMEM2>>>(self_v, out);
}

// round 6
// speedup vs baseline: 4.7456x; 1.3889x over previous
#include <cuda_runtime.h>
#include <cuda_bf16.h>
#include <cstdint>

// ============================================================================
// GlobalAggregator — HMMA bf16 2-way split, padding-free row-major tiling
// B=128, N=128, K=12, D=256; R = B*N*K = 196608 global rows (r = bn*12 + k)
// p1 : Z[r, 0:256] = feat[r,:] @ w1[0:256]; epilogue + wgt[r]*w1[256],
//      lrelu, ·w2, row-reduce -> g_logit[r]          (tile=16 rows, no padding)
// p1b: per bn softmax over 12 logits -> agg = Σ alpha·nbr -> g_agg
// p2 : out = relu(concat(self, agg)[16384,512] @ w3)
// ============================================================================

#define KS1 16
#define KS2 32
#define ROWB 24              // ushorts per n-row: 16 used + 8 pad = 48B
#define CB  (256 * ROWB * 2) // 12288 B per chunk half

// ---- device scratch ----
__device__ __align__(128) unsigned short g_w1t_hi[KS1 * 256 * ROWB];
__device__ __align__(128) unsigned short g_w1t_lo[KS1 * 256 * ROWB];
__device__ __align__(128) unsigned short g_w3t_hi[KS2 * 256 * ROWB];
__device__ __align__(128) unsigned short g_w3t_lo[KS2 * 256 * ROWB];
__device__ __align__(16) float g_agg[16384 * 256];
__device__ __align__(16) float g_logit[196608];

// ---- smem offsets (bytes) ----
#define OFF_B(s) (1024 + (s) * (2 * CB))     // hi @ +0, lo @ +CB
#define OFF_W2   50176
#define OFF_W1L  51200
#define OFF_PART 52224       // 8 warps * 16 rows * 4B
#define SMEM1    52736
#define SMEM2    50176

// ============================================================================
// PTX helpers (baseline features only — nothing 'a'-gated)
// ============================================================================
__device__ __forceinline__ uint32_t smem_u32(const void* p) {
    uint32_t r;
    asm("{ .reg .u64 t; cvta.to.shared.u64 t, %1; cvt.u32.u64 %0, t; }"
        : "=r"(r) : "l"(p));
    return r;
}
__device__ __forceinline__ void mbar_init(uint32_t a, uint32_t cnt) {
    asm volatile("mbarrier.init.shared.b64 [%0], %1;" :: "r"(a), "r"(cnt) : "memory");
}
__device__ __forceinline__ void mbar_expect_tx(uint32_t a, uint32_t b) {
    asm volatile("mbarrier.arrive.expect_tx.shared.b64 _, [%0], %1;"
                 :: "r"(a), "r"(b) : "memory");
}
__device__ __forceinline__ void mbar_wait(uint32_t a, uint32_t ph) {
    asm volatile(
        "{\n\t.reg .pred P;\n\t"
        "WL_%=:\n\t"
        "mbarrier.try_wait.parity.acquire.cta.shared::cta.b64 P, [%0], %1, 0x989680;\n\t"
        "@P bra.uni WD_%=;\n\t"
        "bra.uni WL_%=;\n\t"
        "WD_%=:\n\t}"
        :: "r"(a), "r"(ph) : "memory");
}
__device__ __forceinline__ void bulk_g2s(uint32_t dst, const void* src,
                                         uint32_t bytes, uint32_t mbar) {
    asm volatile(
        "cp.async.bulk.shared::cluster.global.mbarrier::complete_tx::bytes [%0], [%1], %2, [%3];"
        :: "r"(dst), "l"(src), "r"(bytes), "r"(mbar) : "memory");
}
__device__ __forceinline__ void ldsm4(uint32_t* r, uint32_t addr) {
    asm volatile("ldmatrix.sync.aligned.m8n8.x4.shared.b16 {%0,%1,%2,%3}, [%4];"
                 : "=r"(r[0]), "=r"(r[1]), "=r"(r[2]), "=r"(r[3]) : "r"(addr));
}
__device__ __forceinline__ void mma16816(float* c, const uint32_t* a,
                                         uint32_t b0, uint32_t b1) {
    asm volatile(
        "mma.sync.aligned.m16n8k16.row.col.f32.bf16.bf16.f32 "
        "{%0,%1,%2,%3}, {%4,%5,%6,%7}, {%8,%9}, {%0,%1,%2,%3};"
        : "+f"(c[0]), "+f"(c[1]), "+f"(c[2]), "+f"(c[3])
        : "r"(a[0]), "r"(a[1]), "r"(a[2]), "r"(a[3]), "r"(b0), "r"(b1));
}
__device__ __forceinline__ void split2(float v0, float v1, uint32_t& h, uint32_t& l) {
    __nv_bfloat162 hh = __floats2bfloat162_rn(v0, v1);
    float r0 = v0 - __bfloat162float(hh.x);
    float r1 = v1 - __bfloat162float(hh.y);
    __nv_bfloat162 ll = __floats2bfloat162_rn(r0, r1);
    h = *reinterpret_cast<uint32_t*>(&hh);
    l = *reinterpret_cast<uint32_t*>(&ll);
}

// ============================================================================
// prep: transpose + split weights into [chunk][n][k16] (48B rows)
// ============================================================================
__global__ void prep_w1(const float* __restrict__ w1) {
    int i = blockIdx.x * blockDim.x + threadIdx.x;
    if (i >= KS1 * 256 * 16) return;
    int kk = i & 15, n = (i >> 4) & 255, c = i >> 12;
    float v = w1[(c * 16 + kk) * 256 + n];
    __nv_bfloat16 h = __float2bfloat16(v);
    __nv_bfloat16 l = __float2bfloat16(v - __bfloat162float(h));
    int dst = (c * 256 + n) * ROWB + kk;
    g_w1t_hi[dst] = __bfloat16_as_ushort(h);
    g_w1t_lo[dst] = __bfloat16_as_ushort(l);
}
__global__ void prep_w3(const float* __restrict__ w3) {
    int i = blockIdx.x * blockDim.x + threadIdx.x;
    if (i >= KS2 * 256 * 16) return;
    int kk = i & 15, n = (i >> 4) & 255, c = i >> 12;
    float v = w3[(c * 16 + kk) * 256 + n];
    __nv_bfloat16 h = __float2bfloat16(v);
    __nv_bfloat16 l = __float2bfloat16(v - __bfloat162float(h));
    int dst = (c * 256 + n) * ROWB + kk;
    g_w3t_hi[dst] = __bfloat16_as_ushort(h);
    g_w3t_lo[dst] = __bfloat16_as_ushort(l);
}

// ============================================================================
// Phase 1 — grid 3072, 256 thr, 2 CTA/SM. Warp-pair per 16-row tile,
// each warp one N=128 half. Rows are global r (no padding).
// ============================================================================
__global__ __launch_bounds__(256, 2)
void p1_kernel(const float* __restrict__ nbr, const float* __restrict__ wgt,
               const float* __restrict__ extra, const float* __restrict__ w1,
               const float* __restrict__ w2) {
    extern __shared__ char smem[];
    const uint32_t sb = smem_u32(smem);
    const int tid = threadIdx.x, wid = tid >> 5, lane = tid & 31;

    float* s_w2   = (float*)(smem + OFF_W2);
    float* s_w1l  = (float*)(smem + OFF_W1L);
    float* s_part = (float*)(smem + OFF_PART);

    if (tid == 0) { mbar_init(sb + 0, 1); mbar_init(sb + 8, 1); }
    s_w2[tid]  = w2[tid];
    s_w1l[tid] = w1[256 * 256 + tid];
    __syncthreads();

    if (tid == 0) {
        mbar_expect_tx(sb + 0, 2 * CB);
        bulk_g2s(sb + OFF_B(0),      g_w1t_hi, CB, sb + 0);
        bulk_g2s(sb + OFF_B(0) + CB, g_w1t_lo, CB, sb + 0);
        mbar_expect_tx(sb + 8, 2 * CB);
        bulk_g2s(sb + OFF_B(1),      g_w1t_hi + CB / 2, CB, sb + 8);
        bulk_g2s(sb + OFF_B(1) + CB, g_w1t_lo + CB / 2, CB, sb + 8);
    }

    const int  l4  = lane & 3, grp = lane >> 2;
    const long rt  = (long)blockIdx.x * 64 + (wid >> 1) * 16;  // tile base row
    const long r0  = rt + grp, r1 = rt + grp + 8;
    const long bnA = r0 / 12,  bnB = r1 / 12;
    const uint32_t nhoff = (wid & 1) * (128 * ROWB * 2);
    const uint32_t rowoff =
        ((((lane >> 3) & 2) * 4 + (lane & 7)) * ROWB + ((lane >> 3) & 1) * 8) * 2;

    float acc[64];
#pragma unroll
    for (int i = 0; i < 64; i++) acc[i] = 0.0f;

    float2 eA0, eA1, eB0, eB1, nA0, nA1, nB0, nB1;
    {
        const int k0 = l4 * 2;
        eA0 = *(const float2*)&extra[(bnA << 8) + k0];
        eA1 = *(const float2*)&extra[(bnA << 8) + k0 + 8];
        eB0 = *(const float2*)&extra[(bnB << 8) + k0];
        eB1 = *(const float2*)&extra[(bnB << 8) + k0 + 8];
        nA0 = *(const float2*)&nbr[(r0 << 8) + k0];
        nA1 = *(const float2*)&nbr[(r0 << 8) + k0 + 8];
        nB0 = *(const float2*)&nbr[(r1 << 8) + k0];
        nB1 = *(const float2*)&nbr[(r1 << 8) + k0 + 8];
    }

#pragma unroll 1
    for (int c = 0; c < KS1; c++) {
        const int s = c & 1, ph = (c >> 1) & 1;

        uint32_t ah[4], al[4];
        split2(eA0.x * nA0.x, eA0.y * nA0.y, ah[0], al[0]);
        split2(eB0.x * nB0.x, eB0.y * nB0.y, ah[1], al[1]);
        split2(eA1.x * nA1.x, eA1.y * nA1.y, ah[2], al[2]);
        split2(eB1.x * nB1.x, eB1.y * nB1.y, ah[3], al[3]);

        if (c + 1 < KS1) {                       // prefetch next k-step
            const int k0 = (c + 1) * 16 + l4 * 2;
            eA0 = *(const float2*)&extra[(bnA << 8) + k0];
            eA1 = *(const float2*)&extra[(bnA << 8) + k0 + 8];
            eB0 = *(const float2*)&extra[(bnB << 8) + k0];
            eB1 = *(const float2*)&extra[(bnB << 8) + k0 + 8];
            nA0 = *(const float2*)&nbr[(r0 << 8) + k0];
            nA1 = *(const float2*)&nbr[(r0 << 8) + k0 + 8];
            nB0 = *(const float2*)&nbr[(r1 << 8) + k0];
            nB1 = *(const float2*)&nbr[(r1 << 8) + k0 + 8];
        }

        mbar_wait(sb + s * 8, ph);
        const uint32_t sBh = sb + OFF_B(s) + nhoff, sBl = sBh + CB;
#pragma unroll
        for (int np = 0; np < 8; np++) {
            uint32_t bh[4], bl[4];
            ldsm4(bh, sBh + np * (16 * ROWB * 2) + rowoff);
            ldsm4(bl, sBl + np * (16 * ROWB * 2) + rowoff);
            float* c0 = acc + np * 8;
            float* c1 = acc + np * 8 + 4;
            mma16816(c0, ah, bh[0], bh[1]);
            mma16816(c1, ah, bh[2], bh[3]);
            mma16816(c0, al, bh[0], bh[1]);
            mma16816(c1, al, bh[2], bh[3]);
            mma16816(c0, ah, bl[0], bl[1]);
            mma16816(c1, ah, bl[2], bl[3]);
        }
        __syncthreads();
        if (tid == 0 && c + 2 < KS1) {
            mbar_expect_tx(sb + s * 8, 2 * CB);
            bulk_g2s(sb + OFF_B(s),      g_w1t_hi + (c + 2) * (CB / 2), CB, sb + s * 8);
            bulk_g2s(sb + OFF_B(s) + CB, g_w1t_lo + (c + 2) * (CB / 2), CB, sb + s * 8);
        }
    }

    // ---- epilogue: + wgt[r]*w1[256], lrelu, ·w2, reduce over this N-half ----
    const int nh = (wid & 1) * 128;
    const float wr0 = wgt[r0];
    const float wr1 = wgt[r1];
    float p0 = 0.0f, p1 = 0.0f;
#pragma unroll
    for (int nt = 0; nt < 16; nt++) {
        const int col = nh + nt * 8 + l4 * 2;
        const float u0 = s_w1l[col], u1 = s_w1l[col + 1];
        const float v0 = s_w2[col],  v1 = s_w2[col + 1];
        float z;
        z = acc[nt * 4 + 0] + wr0 * u0; z = (z > 0.f) ? z : 0.2f * z; p0 = fmaf(z, v0, p0);
        z = acc[nt * 4 + 1] + wr0 * u1; z = (z > 0.f) ? z : 0.2f * z; p0 = fmaf(z, v1, p0);
        z = acc[nt * 4 + 2] + wr1 * u0; z = (z > 0.f) ? z : 0.2f * z; p1 = fmaf(z, v0, p1);
        z = acc[nt * 4 + 3] + wr1 * u1; z = (z > 0.f) ? z : 0.2f * z; p1 = fmaf(z, v1, p1);
    }
    p0 += __shfl_xor_sync(0xffffffffu, p0, 1);
    p0 += __shfl_xor_sync(0xffffffffu, p0, 2);
    p1 += __shfl_xor_sync(0xffffffffu, p1, 1);
    p1 += __shfl_xor_sync(0xffffffffu, p1, 2);
    if (l4 == 0) {
        s_part[wid * 16 + grp]     = p0;
        s_part[wid * 16 + 8 + grp] = p1;
    }
    __syncthreads();
    if (tid < 64) {   // combine warp-pair halves: 4 tiles * 16 rows
        const int t = tid >> 4, i = tid & 15;
        g_logit[(long)blockIdx.x * 64 + t * 16 + i] =
            s_part[t * 32 + i] + s_part[t * 32 + 16 + i];
    }
}

// ============================================================================
// Phase 1b — softmax over K=12 + aggregation. grid 2048, warp per bn.
// ============================================================================
__global__ __launch_bounds__(256)
void p1b_kernel(const float* __restrict__ nbr) {
    const int tid = threadIdx.x, wid = tid >> 5, lane = tid & 31;
    const long bn = (long)blockIdx.x * 8 + wid;

    float lv = (lane < 12) ? g_logit[bn * 12 + lane] : -3.0e38f;
    float m = lv;
#pragma unroll
    for (int o = 16; o > 0; o >>= 1)
        m = fmaxf(m, __shfl_xor_sync(0xffffffffu, m, o));
    float e = (lane < 12) ? expf(lv - m) : 0.0f;
    float se = e;
#pragma unroll
    for (int o = 16; o > 0; o >>= 1)
        se += __shfl_xor_sync(0xffffffffu, se, o);
    const float a = e / se;

    const int d0 = lane * 8;
    float4 s0 = make_float4(0, 0, 0, 0), s1 = make_float4(0, 0, 0, 0);
#pragma unroll
    for (int k = 0; k < 12; k++) {
        const float ak = __shfl_sync(0xffffffffu, a, k);
        const float4* src = (const float4*)&nbr[((bn * 12 + k) << 8) + d0];
        float4 x = src[0], y = src[1];
        s0.x = fmaf(ak, x.x, s0.x); s0.y = fmaf(ak, x.y, s0.y);
        s0.z = fmaf(ak, x.z, s0.z); s0.w = fmaf(ak, x.w, s0.w);
        s1.x = fmaf(ak, y.x, s1.x); s1.y = fmaf(ak, y.y, s1.y);
        s1.z = fmaf(ak, y.z, s1.z); s1.w = fmaf(ak, y.w, s1.w);
    }
    float4* dst = (float4*)&g_agg[(bn << 8) + d0];
    dst[0] = s0; dst[1] = s1;
}

// ============================================================================
// Phase 2 — grid 256, 256 thr, 2 CTA/SM. Warp-pair per 16-row tile, N=128 half.
// ============================================================================
__global__ __launch_bounds__(256, 2)
void p2_kernel(const float* __restrict__ self_v, float* __restrict__ out) {
    extern __shared__ char smem[];
    const uint32_t sb = smem_u32(smem);
    const int tid = threadIdx.x, wid = tid >> 5, lane = tid & 31;

    if (tid == 0) { mbar_init(sb + 0, 1); mbar_init(sb + 8, 1); }
    __syncthreads();
    if (tid == 0) {
        mbar_expect_tx(sb + 0, 2 * CB);
        bulk_g2s(sb + OFF_B(0),      g_w3t_hi, CB, sb + 0);
        bulk_g2s(sb + OFF_B(0) + CB, g_w3t_lo, CB, sb + 0);
        mbar_expect_tx(sb + 8, 2 * CB);
        bulk_g2s(sb + OFF_B(1),      g_w3t_hi + CB / 2, CB, sb + 8);
        bulk_g2s(sb + OFF_B(1) + CB, g_w3t_lo + CB / 2, CB, sb + 8);
    }

    const int l4 = lane & 3, grp = lane >> 2;
    const long m0 = (long)blockIdx.x * 64 + (wid >> 1) * 16 + grp, m1 = m0 + 8;
    const uint32_t nhoff = (wid & 1) * (128 * ROWB * 2);
    const uint32_t rowoff =
        ((((lane >> 3) & 2) * 4 + (lane & 7)) * ROWB + ((lane >> 3) & 1) * 8) * 2;

    float acc[64];
#pragma unroll
    for (int i = 0; i < 64; i++) acc[i] = 0.0f;

    float2 nA0, nA1, nB0, nB1;
    {
        const int k0 = l4 * 2;
        nA0 = *(const float2*)&self_v[(m0 << 8) + k0];
        nA1 = *(const float2*)&self_v[(m0 << 8) + k0 + 8];
        nB0 = *(const float2*)&self_v[(m1 << 8) + k0];
        nB1 = *(const float2*)&self_v[(m1 << 8) + k0 + 8];
    }

#pragma unroll 1
    for (int c = 0; c < KS2; c++) {
        const int s = c & 1, ph = (c >> 1) & 1;

        uint32_t ah[4], al[4];
        split2(nA0.x, nA0.y, ah[0], al[0]);
        split2(nB0.x, nB0.y, ah[1], al[1]);
        split2(nA1.x, nA1.y, ah[2], al[2]);
        split2(nB1.x, nB1.y, ah[3], al[3]);

        if (c + 1 < KS2) {
            const int cn = c + 1;
            const int k0 = (cn & 15) * 16 + l4 * 2;
            const float* base = (cn < 16) ? self_v : g_agg;
            nA0 = *(const float2*)&base[(m0 << 8) + k0];
            nA1 = *(const float2*)&base[(m0 << 8) + k0 + 8];
            nB0 = *(const float2*)&base[(m1 << 8) + k0];
            nB1 = *(const float2*)&base[(m1 << 8) + k0 + 8];
        }

        mbar_wait(sb + s * 8, ph);
        const uint32_t sBh = sb + OFF_B(s) + nhoff, sBl = sBh + CB;
#pragma unroll
        for (int np = 0; np < 8; np++) {
            uint32_t bh[4], bl[4];
            ldsm4(bh, sBh + np * (16 * ROWB * 2) + rowoff);
            ldsm4(bl, sBl + np * (16 * ROWB * 2) + rowoff);
            float* c0 = acc + np * 8;
            float* c1 = acc + np * 8 + 4;
            mma16816(c0, ah, bh[0], bh[1]);
            mma16816(c1, ah, bh[2], bh[3]);
            mma16816(c0, al, bh[0], bh[1]);
            mma16816(c1, al, bh[2], bh[3]);
            mma16816(c0, ah, bl[0], bl[1]);
            mma16816(c1, ah, bl[2], bl[3]);
        }
        __syncthreads();
        if (tid == 0 && c + 2 < KS2) {
            mbar_expect_tx(sb + s * 8, 2 * CB);
            bulk_g2s(sb + OFF_B(s),      g_w3t_hi + (c + 2) * (CB / 2), CB, sb + s * 8);
            bulk_g2s(sb + OFF_B(s) + CB, g_w3t_lo + (c + 2) * (CB / 2), CB, sb + s * 8);
        }
    }

    const int nh = (wid & 1) * 128;
#pragma unroll
    for (int nt = 0; nt < 16; nt++) {
        const int col = nh + nt * 8 + l4 * 2;
        float2 o0 = make_float2(fmaxf(acc[nt * 4 + 0], 0.f), fmaxf(acc[nt * 4 + 1], 0.f));
        float2 o1 = make_float2(fmaxf(acc[nt * 4 + 2], 0.f), fmaxf(acc[nt * 4 + 3], 0.f));
        *(float2*)&out[(m0 << 8) + col] = o0;
        *(float2*)&out[(m1 << 8) + col] = o1;
    }
}

// ============================================================================
extern "C" void kernel_launch(void* const* d_in, const int* in_sizes, int n_in,
                              void* d_out, int out_size) {
    const float* self_v = (const float*)d_in[0];
    const float* nbr    = (const float*)d_in[1];
    // d_in[2] = masks (unused by reference)
    const float* wgt    = (const float*)d_in[3];
    const float* extra  = (const float*)d_in[4];
    const float* w1     = (const float*)d_in[5];
    const float* w2     = (const float*)d_in[6];
    const float* w3     = (const float*)d_in[7];
    float* out = (float*)d_out;

    cudaFuncSetAttribute(p1_kernel, cudaFuncAttributeMaxDynamicSharedMemorySize, SMEM1);
    cudaFuncSetAttribute(p2_kernel, cudaFuncAttributeMaxDynamicSharedMemorySize, SMEM2);

    prep_w1<<<256, 256>>>(w1);
    prep_w3<<<512, 256>>>(w3);
    p1_kernel<<<3072, 256, SMEM1>>>(nbr, wgt, extra, w1, w2);
    p1b_kernel<<<2048, 256>>>(nbr);
    p2_kernel<<<256, 256, SMEM2>>>(self_v, out);
}